// round 1
// baseline (speedup 1.0000x reference)
#include <cuda_runtime.h>
#include <math.h>
#include <stdint.h>

// Problem constants
#define NQPT   20000   // queries
#define SSUP   20000   // supports (== shadow index)
#define NNB    30      // neighbors
#define NKP    15      // kernel points
#define NQL    4       // query LRFs
#define LRFC   32
#define CINF   128
#define FDIMC  256     // 2*CIN... actually NQ*64
#define COUTC  256
#define EXT_INV 20.0f  // 1/0.05

// Scratch: weighted features [N][K][256]  (k*256 + q*64 + c)
__device__ float g_scratch[(size_t)NQPT * NKP * 256];

// ---------------------------------------------------------------------------
// Stage 1: per-query block. Computes KP influence weights, LRF features,
// and weighted = w @ feat, written to g_scratch.
// ---------------------------------------------------------------------------
struct S1 {
    float A[4][36][32];        // 18432 B : A[q][t=(s,k,j)][c] = sum_i ql[q,k,i]*Wl[s*9+i*3+j][c]
    float w[4][NNB][16];       //  7680 B : KP weights, k padded to 16 (w[..][15]=0)
    float lrff[NNB][4][32];    // 15360 B : LRF feature half (already masked, bias added)
    float nblrf[NNB][36];      //  4320 B : gathered s_lrf (masked)
    float ql[36];
    float kp[45];
    float qp[3];
    float bl[32];
    float nb[NNB][3];
    float mask[NNB];
    int   ic[NNB];
};

__global__ __launch_bounds__(256)
void ekp_stage1(const float* __restrict__ q_pts, const float* __restrict__ s_pts,
                const int*   __restrict__ nidx,  const float* __restrict__ x,
                const float* __restrict__ q_lrf, const float* __restrict__ s_lrf,
                const float* __restrict__ kpt,   const float* __restrict__ W_lrf,
                const float* __restrict__ b_lrf)
{
    __shared__ S1 s;
    const int n   = blockIdx.x;
    const int tid = threadIdx.x;

    // ---- Phase A: independent loads ----
    if (tid < 36)                    s.ql[tid]      = q_lrf[n * 36 + tid];
    if (tid >= 64  && tid < 64+45)   s.kp[tid-64]   = kpt[tid - 64];
    if (tid >= 112 && tid < 115)     s.qp[tid-112]  = q_pts[n * 3 + (tid - 112)];
    if (tid >= 128 && tid < 160)     s.bl[tid-128]  = b_lrf[tid - 128];
    if (tid >= 160 && tid < 160+NNB) {
        int m   = tid - 160;
        int raw = nidx[n * NNB + m];
        bool ok = raw < SSUP;
        s.ic[m]   = ok ? raw : 0;
        s.mask[m] = ok ? 1.0f : 0.0f;
    }
    __syncthreads();

    // ---- Phase B: gathers + A precompute ----
    if (tid < NNB) {
        int m = tid;
        int base = s.ic[m] * 3;
        s.nb[m][0] = s_pts[base + 0] - s.qp[0];
        s.nb[m][1] = s_pts[base + 1] - s.qp[1];
        s.nb[m][2] = s_pts[base + 2] - s.qp[2];
    }
    for (int e = tid; e < NNB * 36; e += 256) {
        int m = e / 36, t = e % 36;
        s.nblrf[m][t] = s_lrf[(size_t)s.ic[m] * 36 + t] * s.mask[m];
    }
    // A[q][t][c], t=(sL,kk,j): sum_i ql[q,kk,i] * Wl[(sL*9+i*3+j)*32 + c]
    for (int e = tid; e < 4 * 36 * 32; e += 256) {
        int cc = e & 31;
        int t  = (e >> 5) % 36;
        int q  = e / (36 * 32);
        int sL = t / 9, r = t % 9, kk = r / 3, j = r % 3;
        float sum = 0.f;
        #pragma unroll
        for (int i = 0; i < 3; ++i)
            sum += s.ql[q*9 + kk*3 + i] * __ldg(&W_lrf[(sL*9 + i*3 + j) * 32 + cc]);
        s.A[q][t][cc] = sum;
    }
    __syncthreads();

    // ---- Phase C: KP weights (threads 0..119)  ||  LRF features (threads 128..247) ----
    if (tid < 120) {
        int q = tid / 30, m = tid % 30;
        float a0 = 0.f, a1 = 0.f, a2 = 0.f;
        #pragma unroll
        for (int i = 0; i < 3; ++i) {
            float v = s.nb[m][i];
            a0 += v * s.ql[q*9 + i*3 + 0];
            a1 += v * s.ql[q*9 + i*3 + 1];
            a2 += v * s.ql[q*9 + i*3 + 2];
        }
        float msk = s.mask[m];
        #pragma unroll
        for (int k = 0; k < NKP; ++k) {
            float d0 = a0 - s.kp[k*3 + 0];
            float d1 = a1 - s.kp[k*3 + 1];
            float d2 = a2 - s.kp[k*3 + 2];
            float d  = sqrtf(d0*d0 + d1*d1 + d2*d2);
            s.w[q][m][k] = fmaxf(1.0f - d * EXT_INV, 0.0f) * msk;
        }
        s.w[q][m][15] = 0.0f;
    } else if (tid >= 128 && tid < 248) {
        int e = tid - 128;          // 0..119
        int m = e >> 2;             // 0..29
        int q = e & 3;              // 0..3
        float acc[32];
        #pragma unroll
        for (int cc = 0; cc < 32; ++cc) acc[cc] = 0.f;
        #pragma unroll 4
        for (int t = 0; t < 36; ++t) {
            float v = s.nblrf[m][t];
            const float4* Ar = reinterpret_cast<const float4*>(&s.A[q][t][0]);
            #pragma unroll
            for (int c4 = 0; c4 < 8; ++c4) {
                float4 a = Ar[c4];
                acc[c4*4 + 0] += v * a.x;
                acc[c4*4 + 1] += v * a.y;
                acc[c4*4 + 2] += v * a.z;
                acc[c4*4 + 3] += v * a.w;
            }
        }
        float msk = s.mask[m];
        #pragma unroll
        for (int cc = 0; cc < 32; ++cc)
            s.lrff[m][q][cc] = (acc[cc] + s.bl[cc]) * msk;
    }
    __syncthreads();

    // ---- Phase D: weighted[q][k][c] = sum_m w[q][k][m] * feat[q][m][c] ----
    // thread -> (q, cg, ks): 4 c-cols (cg) x 4 k-rows (ks). Whole warps are
    // uniformly x-branch (cg<8) or lrf-branch (cg>=8).
    {
        int q  = tid >> 6;
        int cg = (tid >> 2) & 15;
        int ks = tid & 3;
        float acc[4][4];
        #pragma unroll
        for (int i = 0; i < 4; ++i)
            #pragma unroll
            for (int j = 0; j < 4; ++j) acc[i][j] = 0.f;

        const float4* xp = reinterpret_cast<const float4*>(x);

        #pragma unroll 5
        for (int m = 0; m < NNB; ++m) {
            float4 f;
            if (cg < 8) {
                f = __ldg(&xp[(size_t)s.ic[m] * 32 + q * 8 + cg]);
                float msk = s.mask[m];
                f.x *= msk; f.y *= msk; f.z *= msk; f.w *= msk;
            } else {
                f = *reinterpret_cast<const float4*>(&s.lrff[m][q][(cg - 8) * 4]);
            }
            float4 wv = *reinterpret_cast<const float4*>(&s.w[q][m][ks * 4]);
            acc[0][0] += wv.x * f.x; acc[0][1] += wv.x * f.y; acc[0][2] += wv.x * f.z; acc[0][3] += wv.x * f.w;
            acc[1][0] += wv.y * f.x; acc[1][1] += wv.y * f.y; acc[1][2] += wv.y * f.z; acc[1][3] += wv.y * f.w;
            acc[2][0] += wv.z * f.x; acc[2][1] += wv.z * f.y; acc[2][2] += wv.z * f.z; acc[2][3] += wv.z * f.w;
            acc[3][0] += wv.w * f.x; acc[3][1] += wv.w * f.y; acc[3][2] += wv.w * f.z; acc[3][3] += wv.w * f.w;
        }

        // scratch[n][k][q*64 + cg*4 .. +3], f4 index: k*64 + q*16 + cg
        float4* outp = reinterpret_cast<float4*>(g_scratch + (size_t)n * (NKP * 256));
        #pragma unroll
        for (int kk = 0; kk < 4; ++kk) {
            int k = ks * 4 + kk;
            if (k < NKP) {
                float4 v = make_float4(acc[kk][0], acc[kk][1], acc[kk][2], acc[kk][3]);
                outp[k * 64 + q * 16 + cg] = v;
            }
        }
    }
}

// ---------------------------------------------------------------------------
// Stage 2: out[N,256] = scratch[N,3840] @ weights[3840,256] + bias, LeakyReLU.
// Classic fp32 SGEMM: BM=128, BN=64, BK=16, 256 threads, 8x4 microtile.
// ---------------------------------------------------------------------------
#define BM 128
#define BN 64
#define BK 16
#define KTOT (NKP * 256)   // 3840

__global__ __launch_bounds__(256)
void ekp_stage2(const float* __restrict__ Wt, const float* __restrict__ bias,
                float* __restrict__ out)
{
    __shared__ float As[BK][BM + 4];   // transposed tile, padded (float4-aligned)
    __shared__ float Bs[BK][BN];

    const float* Amat = g_scratch;
    const int block_row = blockIdx.x * BM;
    const int block_col = blockIdx.y * BN;
    const int tid = threadIdx.x;
    const int ty = tid >> 4;    // 0..15
    const int tx = tid & 15;    // 0..15

    float acc[8][4];
    #pragma unroll
    for (int i = 0; i < 8; ++i)
        #pragma unroll
        for (int j = 0; j < 4; ++j) acc[i][j] = 0.f;

    for (int k0 = 0; k0 < KTOT; k0 += BK) {
        // A tile: 128 x 16 floats = 512 float4
        #pragma unroll
        for (int l = 0; l < 2; ++l) {
            int e  = tid + l * 256;      // 0..511
            int r  = e >> 2;             // 0..127
            int c4 = (e & 3) * 4;        // 0,4,8,12
            int grow = block_row + r;
            float4 v = make_float4(0.f, 0.f, 0.f, 0.f);
            if (grow < NQPT)
                v = *reinterpret_cast<const float4*>(&Amat[(size_t)grow * KTOT + k0 + c4]);
            As[c4 + 0][r] = v.x;
            As[c4 + 1][r] = v.y;
            As[c4 + 2][r] = v.z;
            As[c4 + 3][r] = v.w;
        }
        // B tile: 16 x 64 floats = 256 float4
        {
            int r  = tid >> 4;           // 0..15
            int c4 = (tid & 15) * 4;     // 0..60
            *reinterpret_cast<float4*>(&Bs[r][c4]) =
                *reinterpret_cast<const float4*>(&Wt[(size_t)(k0 + r) * 256 + block_col + c4]);
        }
        __syncthreads();

        #pragma unroll
        for (int kk = 0; kk < BK; ++kk) {
            float4 a0 = *reinterpret_cast<const float4*>(&As[kk][ty * 8]);
            float4 a1 = *reinterpret_cast<const float4*>(&As[kk][ty * 8 + 4]);
            float4 b  = *reinterpret_cast<const float4*>(&Bs[kk][tx * 4]);
            float av[8] = {a0.x, a0.y, a0.z, a0.w, a1.x, a1.y, a1.z, a1.w};
            float bv[4] = {b.x, b.y, b.z, b.w};
            #pragma unroll
            for (int i = 0; i < 8; ++i)
                #pragma unroll
                for (int j = 0; j < 4; ++j)
                    acc[i][j] += av[i] * bv[j];
        }
        __syncthreads();
    }

    // Epilogue: bias + LeakyReLU(0.1)
    #pragma unroll
    for (int i = 0; i < 8; ++i) {
        int grow = block_row + ty * 8 + i;
        if (grow >= NQPT) continue;
        #pragma unroll
        for (int j = 0; j < 4; ++j) {
            int gcol = block_col + tx * 4 + j;
            float v = acc[i][j] + __ldg(&bias[gcol]);
            out[(size_t)grow * 256 + gcol] = (v >= 0.f) ? v : 0.1f * v;
        }
    }
}

// ---------------------------------------------------------------------------
extern "C" void kernel_launch(void* const* d_in, const int* in_sizes, int n_in,
                              void* d_out, int out_size)
{
    const float* q_pts = (const float*)d_in[0];
    const float* s_pts = (const float*)d_in[1];
    const int*   nind  = (const int*)  d_in[2];
    const float* x     = (const float*)d_in[3];
    const float* q_lrf = (const float*)d_in[4];
    const float* s_lrf = (const float*)d_in[5];
    const float* kpt   = (const float*)d_in[6];
    const float* wts   = (const float*)d_in[7];
    const float* W_lrf = (const float*)d_in[8];
    const float* b_lrf = (const float*)d_in[9];
    const float* bias  = (const float*)d_in[10];
    float* out = (float*)d_out;

    ekp_stage1<<<NQPT, 256>>>(q_pts, s_pts, nind, x, q_lrf, s_lrf, kpt, W_lrf, b_lrf);

    dim3 g2((NQPT + BM - 1) / BM, COUTC / BN);   // (157, 4)
    ekp_stage2<<<g2, 256>>>(wts, bias, out);
}

// round 3
// speedup vs baseline: 2.1765x; 2.1765x over previous
#include <cuda_runtime.h>
#include <math.h>
#include <stdint.h>

// Problem constants
#define NQPT   20000
#define SSUP   20000
#define NNB    30
#define NKP    15
#define EXT_INV 20.0f
#define KTOT   (NKP * 256)   // 3840
#define COUTC  256

// Scratch: weighted features [N][K*256]
__device__ float g_scratch[(size_t)NQPT * KTOT];

// ---------------------------------------------------------------------------
// Helpers
// ---------------------------------------------------------------------------
static __device__ __forceinline__ uint32_t smem_u32(const void* p) {
    uint32_t a;
    asm("{ .reg .u64 t; cvta.to.shared.u64 t, %1; cvt.u32.u64 %0, t; }" : "=r"(a) : "l"(p));
    return a;
}
static __device__ __forceinline__ void cpa16(uint32_t s, const void* g) {
    asm volatile("cp.async.cg.shared.global [%0], [%1], 16;" :: "r"(s), "l"(g));
}
#define CP_COMMIT() asm volatile("cp.async.commit_group;" ::: "memory")
#define CP_WAIT1()  asm volatile("cp.async.wait_group 1;"  ::: "memory")
#define CP_WAIT0()  asm volatile("cp.async.wait_group 0;"  ::: "memory")

static __device__ __forceinline__ uint32_t f2tf32(float f) {
    uint32_t u;
    asm("cvt.rna.tf32.f32 %0, %1;" : "=r"(u) : "f"(f));
    return u;
}
static __device__ __forceinline__ void mma16n8k8(float* d, const uint32_t* a, const uint32_t* b) {
    asm volatile(
        "mma.sync.aligned.m16n8k8.row.col.f32.tf32.tf32.f32 "
        "{%0,%1,%2,%3}, {%4,%5,%6,%7}, {%8,%9}, {%0,%1,%2,%3};"
        : "+f"(d[0]), "+f"(d[1]), "+f"(d[2]), "+f"(d[3])
        : "r"(a[0]), "r"(a[1]), "r"(a[2]), "r"(a[3]), "r"(b[0]), "r"(b[1]));
}

// ---------------------------------------------------------------------------
// Stage 1 (AQ padding kills the 4-way LDS conflict on A reads)
// ---------------------------------------------------------------------------
#define AQ 1160   // per-q stride of A in floats: 36*32 + 8 pad -> bank offset 8 per q

struct S1 {
    float A[4 * AQ];
    float w[4][NNB][16];
    float lrff[NNB][4][32];
    float nblrf[NNB][36];
    float ql[36];
    float kp[45];
    float qp[3];
    float bl[32];
    float nb[NNB][3];
    float mask[NNB];
    int   ic[NNB];
};

__global__ __launch_bounds__(256)
void ekp_stage1(const float* __restrict__ q_pts, const float* __restrict__ s_pts,
                const int*   __restrict__ nidx,  const float* __restrict__ x,
                const float* __restrict__ q_lrf, const float* __restrict__ s_lrf,
                const float* __restrict__ kpt,   const float* __restrict__ W_lrf,
                const float* __restrict__ b_lrf)
{
    __shared__ S1 s;
    const int n   = blockIdx.x;
    const int tid = threadIdx.x;

    if (tid < 36)                    s.ql[tid]      = q_lrf[n * 36 + tid];
    if (tid >= 64  && tid < 64+45)   s.kp[tid-64]   = kpt[tid - 64];
    if (tid >= 112 && tid < 115)     s.qp[tid-112]  = q_pts[n * 3 + (tid - 112)];
    if (tid >= 128 && tid < 160)     s.bl[tid-128]  = b_lrf[tid - 128];
    if (tid >= 160 && tid < 160+NNB) {
        int m   = tid - 160;
        int raw = nidx[n * NNB + m];
        bool ok = raw < SSUP;
        s.ic[m]   = ok ? raw : 0;
        s.mask[m] = ok ? 1.0f : 0.0f;
    }
    __syncthreads();

    if (tid < NNB) {
        int m = tid;
        int base = s.ic[m] * 3;
        s.nb[m][0] = s_pts[base + 0] - s.qp[0];
        s.nb[m][1] = s_pts[base + 1] - s.qp[1];
        s.nb[m][2] = s_pts[base + 2] - s.qp[2];
    }
    for (int e = tid; e < NNB * 36; e += 256) {
        int m = e / 36, t = e % 36;
        s.nblrf[m][t] = s_lrf[(size_t)s.ic[m] * 36 + t] * s.mask[m];
    }
    for (int e = tid; e < 4 * 36 * 32; e += 256) {
        int cc = e & 31;
        int t  = (e >> 5) % 36;
        int q  = e / (36 * 32);
        int sL = t / 9, r = t % 9, kk = r / 3, j = r % 3;
        float sum = 0.f;
        #pragma unroll
        for (int i = 0; i < 3; ++i)
            sum += s.ql[q*9 + kk*3 + i] * __ldg(&W_lrf[(sL*9 + i*3 + j) * 32 + cc]);
        s.A[q * AQ + t * 32 + cc] = sum;
    }
    __syncthreads();

    if (tid < 120) {
        int q = tid / 30, m = tid % 30;
        float a0 = 0.f, a1 = 0.f, a2 = 0.f;
        #pragma unroll
        for (int i = 0; i < 3; ++i) {
            float v = s.nb[m][i];
            a0 += v * s.ql[q*9 + i*3 + 0];
            a1 += v * s.ql[q*9 + i*3 + 1];
            a2 += v * s.ql[q*9 + i*3 + 2];
        }
        float msk = s.mask[m];
        #pragma unroll
        for (int k = 0; k < NKP; ++k) {
            float d0 = a0 - s.kp[k*3 + 0];
            float d1 = a1 - s.kp[k*3 + 1];
            float d2 = a2 - s.kp[k*3 + 2];
            float d  = sqrtf(d0*d0 + d1*d1 + d2*d2);
            s.w[q][m][k] = fmaxf(1.0f - d * EXT_INV, 0.0f) * msk;
        }
        s.w[q][m][15] = 0.0f;
    } else if (tid >= 128 && tid < 248) {
        int e = tid - 128;
        int m = e >> 2;
        int q = e & 3;
        float acc[32];
        #pragma unroll
        for (int cc = 0; cc < 32; ++cc) acc[cc] = 0.f;
        #pragma unroll 4
        for (int t = 0; t < 36; ++t) {
            float v = s.nblrf[m][t];
            const float4* Ar = reinterpret_cast<const float4*>(&s.A[q * AQ + t * 32]);
            #pragma unroll
            for (int c4 = 0; c4 < 8; ++c4) {
                float4 a = Ar[c4];
                acc[c4*4 + 0] += v * a.x;
                acc[c4*4 + 1] += v * a.y;
                acc[c4*4 + 2] += v * a.z;
                acc[c4*4 + 3] += v * a.w;
            }
        }
        float msk = s.mask[m];
        #pragma unroll
        for (int cc = 0; cc < 32; ++cc)
            s.lrff[m][q][cc] = (acc[cc] + s.bl[cc]) * msk;
    }
    __syncthreads();

    {
        int q  = tid >> 6;
        int cg = (tid >> 2) & 15;
        int ks = tid & 3;
        float acc[4][4];
        #pragma unroll
        for (int i = 0; i < 4; ++i)
            #pragma unroll
            for (int j = 0; j < 4; ++j) acc[i][j] = 0.f;

        const float4* xp = reinterpret_cast<const float4*>(x);

        #pragma unroll 5
        for (int m = 0; m < NNB; ++m) {
            float4 f;
            if (cg < 8) {
                f = __ldg(&xp[(size_t)s.ic[m] * 32 + q * 8 + cg]);
                float msk = s.mask[m];
                f.x *= msk; f.y *= msk; f.z *= msk; f.w *= msk;
            } else {
                f = *reinterpret_cast<const float4*>(&s.lrff[m][q][(cg - 8) * 4]);
            }
            float4 wv = *reinterpret_cast<const float4*>(&s.w[q][m][ks * 4]);
            acc[0][0] += wv.x * f.x; acc[0][1] += wv.x * f.y; acc[0][2] += wv.x * f.z; acc[0][3] += wv.x * f.w;
            acc[1][0] += wv.y * f.x; acc[1][1] += wv.y * f.y; acc[1][2] += wv.y * f.z; acc[1][3] += wv.y * f.w;
            acc[2][0] += wv.z * f.x; acc[2][1] += wv.z * f.y; acc[2][2] += wv.z * f.z; acc[2][3] += wv.z * f.w;
            acc[3][0] += wv.w * f.x; acc[3][1] += wv.w * f.y; acc[3][2] += wv.w * f.z; acc[3][3] += wv.w * f.w;
        }

        float4* outp = reinterpret_cast<float4*>(g_scratch + (size_t)n * KTOT);
        #pragma unroll
        for (int kk = 0; kk < 4; ++kk) {
            int k = ks * 4 + kk;
            if (k < NKP) {
                float4 v = make_float4(acc[kk][0], acc[kk][1], acc[kk][2], acc[kk][3]);
                outp[k * 64 + q * 16 + cg] = v;
            }
        }
    }
}

// ---------------------------------------------------------------------------
// Stage 2: tf32 mma.sync GEMM.
//   out[20000,256] = scratch[20000,3840] @ weights[3840,256]; bias+LeakyReLU.
//   CTA 128x128x16, 8 warps (4m x 2n), warp tile 32x64, cp.async dbl-buffer.
// ---------------------------------------------------------------------------
#define S2_BM   128
#define S2_BN   128
#define S2_AST  20     // A smem row stride (floats): conflict-free frag loads
#define S2_BST  132    // B smem row stride (floats)
#define S2_KIT  (KTOT / 16)   // 240

__global__ __launch_bounds__(256, 2)
void ekp_stage2_mma(const float* __restrict__ W, const float* __restrict__ bias,
                    float* __restrict__ out)
{
    __shared__ float As[2][S2_BM * S2_AST];   // [m][k] padded
    __shared__ float Bs[2][16 * S2_BST];      // [k][n] padded

    const int tid  = threadIdx.x;
    const int lane = tid & 31;
    const int wid  = tid >> 5;
    const int wm   = wid & 3;        // warp m index (0..3)
    const int wn   = wid >> 2;       // warp n index (0..1)
    const int gid  = lane >> 2;      // 0..7
    const int tig  = lane & 3;       // 0..3
    const int n0   = blockIdx.x * S2_BN;
    const int row0 = blockIdx.y * S2_BM;

    const uint32_t aSm = smem_u32(&As[0][0]);
    const uint32_t bSm = smem_u32(&Bs[0][0]);

    float acc[2][8][4];
    #pragma unroll
    for (int i = 0; i < 2; ++i)
        #pragma unroll
        for (int j = 0; j < 8; ++j)
            #pragma unroll
            for (int l = 0; l < 4; ++l) acc[i][j][l] = 0.f;

    // A loads: 512 16B chunks; chunk -> (r = ch/4, c = ch%4)
    int aR = tid >> 2, aC = tid & 3;
    int aRow0 = row0 + aR;           int aRow1 = row0 + aR + 64;
    if (aRow0 > NQPT - 1) aRow0 = NQPT - 1;
    if (aRow1 > NQPT - 1) aRow1 = NQPT - 1;
    const float* aG0 = g_scratch + (size_t)aRow0 * KTOT + aC * 4;
    const float* aG1 = g_scratch + (size_t)aRow1 * KTOT + aC * 4;
    uint32_t aS0 = aSm + (uint32_t)(aR * S2_AST + aC * 4) * 4;
    uint32_t aS1 = aSm + (uint32_t)((aR + 64) * S2_AST + aC * 4) * 4;
    // B loads: 512 chunks; (r = ch/32, c = ch%32)
    int bR = tid >> 5, bC = tid & 31;
    const float* bG0 = W + (size_t)bR * COUTC + n0 + bC * 4;
    const float* bG1 = W + (size_t)(bR + 8) * COUTC + n0 + bC * 4;
    uint32_t bS0 = bSm + (uint32_t)(bR * S2_BST + bC * 4) * 4;
    uint32_t bS1 = bSm + (uint32_t)((bR + 8) * S2_BST + bC * 4) * 4;

    const uint32_t aBufStride = (uint32_t)(S2_BM * S2_AST) * 4;
    const uint32_t bBufStride = (uint32_t)(16 * S2_BST) * 4;

    auto load_tile = [&](int kt, int buf) {
        int k0 = kt * 16;
        cpa16(aS0 + buf * aBufStride, aG0 + k0);
        cpa16(aS1 + buf * aBufStride, aG1 + k0);
        cpa16(bS0 + buf * bBufStride, bG0 + (size_t)k0 * COUTC);
        cpa16(bS1 + buf * bBufStride, bG1 + (size_t)k0 * COUTC);
    };

    load_tile(0, 0);
    CP_COMMIT();

    for (int kt = 0; kt < S2_KIT; ++kt) {
        const int buf = kt & 1;
        if (kt + 1 < S2_KIT) {
            load_tile(kt + 1, buf ^ 1);
            CP_COMMIT();
            CP_WAIT1();
        } else {
            CP_WAIT0();
        }
        __syncthreads();

        const float* Ab = &As[buf][0];
        const float* Bb = &Bs[buf][0];
        #pragma unroll
        for (int ks = 0; ks < 16; ks += 8) {
            uint32_t a[2][4];
            #pragma unroll
            for (int mt = 0; mt < 2; ++mt) {
                int mbase = (wm * 32 + mt * 16 + gid) * S2_AST + ks + tig;
                a[mt][0] = f2tf32(Ab[mbase]);
                a[mt][1] = f2tf32(Ab[mbase + 8 * S2_AST]);
                a[mt][2] = f2tf32(Ab[mbase + 4]);
                a[mt][3] = f2tf32(Ab[mbase + 8 * S2_AST + 4]);
            }
            #pragma unroll
            for (int nt = 0; nt < 8; ++nt) {
                int nb = wn * 64 + nt * 8 + gid;
                uint32_t b[2];
                b[0] = f2tf32(Bb[(ks + tig) * S2_BST + nb]);
                b[1] = f2tf32(Bb[(ks + tig + 4) * S2_BST + nb]);
                mma16n8k8(acc[0][nt], a[0], b);
                mma16n8k8(acc[1][nt], a[1], b);
            }
        }
        __syncthreads();
    }

    // Epilogue: bias + LeakyReLU(0.1)
    #pragma unroll
    for (int mt = 0; mt < 2; ++mt) {
        int r0 = row0 + wm * 32 + mt * 16 + gid;
        #pragma unroll
        for (int nt = 0; nt < 8; ++nt) {
            int col = n0 + wn * 64 + nt * 8 + 2 * tig;
            float2 bb = *reinterpret_cast<const float2*>(&bias[col]);
            float v0 = acc[mt][nt][0] + bb.x;
            float v1 = acc[mt][nt][1] + bb.y;
            float v2 = acc[mt][nt][2] + bb.x;
            float v3 = acc[mt][nt][3] + bb.y;
            v0 = (v0 >= 0.f) ? v0 : 0.1f * v0;
            v1 = (v1 >= 0.f) ? v1 : 0.1f * v1;
            v2 = (v2 >= 0.f) ? v2 : 0.1f * v2;
            v3 = (v3 >= 0.f) ? v3 : 0.1f * v3;
            if (r0 < NQPT)
                *reinterpret_cast<float2*>(&out[(size_t)r0 * COUTC + col]) = make_float2(v0, v1);
            if (r0 + 8 < NQPT)
                *reinterpret_cast<float2*>(&out[(size_t)(r0 + 8) * COUTC + col]) = make_float2(v2, v3);
        }
    }
}

// ---------------------------------------------------------------------------
extern "C" void kernel_launch(void* const* d_in, const int* in_sizes, int n_in,
                              void* d_out, int out_size)
{
    const float* q_pts = (const float*)d_in[0];
    const float* s_pts = (const float*)d_in[1];
    const int*   nind  = (const int*)  d_in[2];
    const float* x     = (const float*)d_in[3];
    const float* q_lrf = (const float*)d_in[4];
    const float* s_lrf = (const float*)d_in[5];
    const float* kpt   = (const float*)d_in[6];
    const float* wts   = (const float*)d_in[7];
    const float* W_lrf = (const float*)d_in[8];
    const float* b_lrf = (const float*)d_in[9];
    const float* bias  = (const float*)d_in[10];
    float* out = (float*)d_out;

    ekp_stage1<<<NQPT, 256>>>(q_pts, s_pts, nind, x, q_lrf, s_lrf, kpt, W_lrf, b_lrf);

    dim3 g2(COUTC / S2_BN, (NQPT + S2_BM - 1) / S2_BM);   // (2, 157)
    ekp_stage2_mma<<<g2, 256>>>(wts, bias, out);
}

// round 4
// speedup vs baseline: 3.5348x; 1.6241x over previous
#include <cuda_runtime.h>
#include <math.h>
#include <stdint.h>

// Problem constants
#define NQPT   20000
#define SSUP   20000
#define NNB    30
#define NKP    15
#define EXT_INV 20.0f
#define KTOT   (NKP * 256)   // 3840
#define COUTC  256

__device__ float g_scratch[(size_t)NQPT * KTOT];   // tf32-rounded stage1 output
__device__ float g_T[(size_t)SSUP * 288];          // per-support LRF projection [spt][9][32]
__device__ float g_Wc[(size_t)KTOT * COUTC];       // tf32-rounded weights

// ---------------------------------------------------------------------------
// Helpers
// ---------------------------------------------------------------------------
static __device__ __forceinline__ uint32_t smem_u32(const void* p) {
    uint32_t a;
    asm("{ .reg .u64 t; cvta.to.shared.u64 t, %1; cvt.u32.u64 %0, t; }" : "=r"(a) : "l"(p));
    return a;
}
static __device__ __forceinline__ void cpa16(uint32_t s, const void* g) {
    asm volatile("cp.async.cg.shared.global [%0], [%1], 16;" :: "r"(s), "l"(g));
}
#define CP_COMMIT() asm volatile("cp.async.commit_group;" ::: "memory")
#define CP_WAIT1()  asm volatile("cp.async.wait_group 1;"  ::: "memory")
#define CP_WAIT0()  asm volatile("cp.async.wait_group 0;"  ::: "memory")

static __device__ __forceinline__ uint32_t f2tf32(float f) {
    uint32_t u;
    asm("cvt.rna.tf32.f32 %0, %1;" : "=r"(u) : "f"(f));
    return u;
}
static __device__ __forceinline__ void mma16n8k8(float* d, const uint32_t* a, const uint32_t* b) {
    asm volatile(
        "mma.sync.aligned.m16n8k8.row.col.f32.tf32.tf32.f32 "
        "{%0,%1,%2,%3}, {%4,%5,%6,%7}, {%8,%9}, {%0,%1,%2,%3};"
        : "+f"(d[0]), "+f"(d[1]), "+f"(d[2]), "+f"(d[3])
        : "r"(a[0]), "r"(a[1]), "r"(a[2]), "r"(a[3]), "r"(b[0]), "r"(b[1]));
}

// ---------------------------------------------------------------------------
// Prep A: T[spt][(k*3+i)][c] = sum_{s,j} s_lrf[spt][s*9+k*3+j] * W_lrf[(s*9+i*3+j)*32+c]
// ---------------------------------------------------------------------------
__global__ __launch_bounds__(256)
void build_T(const float* __restrict__ s_lrf, const float* __restrict__ W_lrf)
{
    __shared__ float Wsh[36 * 32];
    const int tid = threadIdx.x;
    for (int i = tid; i < 36 * 32; i += 256) Wsh[i] = W_lrf[i];
    __syncthreads();

    const int warp = tid >> 5, lane = tid & 31;
    const int spt = blockIdx.x * 8 + warp;
    if (spt >= SSUP) return;

    const float* sl = s_lrf + (size_t)spt * 36;
    float slr[36];
    #pragma unroll
    for (int i = 0; i < 36; ++i) slr[i] = __ldg(&sl[i]);

    float* Tout = g_T + (size_t)spt * 288;
    #pragma unroll
    for (int k = 0; k < 3; ++k) {
        #pragma unroll
        for (int i = 0; i < 3; ++i) {
            float acc = 0.f;
            #pragma unroll
            for (int s = 0; s < 4; ++s)
                #pragma unroll
                for (int j = 0; j < 3; ++j)
                    acc += slr[s*9 + k*3 + j] * Wsh[(s*9 + i*3 + j) * 32 + lane];
            Tout[(k*3 + i) * 32 + lane] = acc;
        }
    }
}

// Prep B: round weights to tf32 once
__global__ __launch_bounds__(256)
void conv_w(const float* __restrict__ W)
{
    size_t i = (size_t)blockIdx.x * 256 + threadIdx.x;
    if (i < (size_t)KTOT * COUTC)
        g_Wc[i] = __uint_as_float(f2tf32(W[i]));
}

// ---------------------------------------------------------------------------
// Stage 1: per-query block.
// ---------------------------------------------------------------------------
struct S1 {
    float w[4][NNB][16];       //  7680 B : KP weights, k padded to 16
    float lrff[NNB][4][32];    // 15360 B : LRF feature half (masked, bias added)
    float ql[36];
    float kp[45];
    float qp[3];
    float bl[32];
    float nb[NNB][3];
    float mask[NNB];
    int   ic[NNB];
};

__global__ __launch_bounds__(256)
void ekp_stage1(const float* __restrict__ q_pts, const float* __restrict__ s_pts,
                const int*   __restrict__ nidx,  const float* __restrict__ x,
                const float* __restrict__ q_lrf, const float* __restrict__ kpt,
                const float* __restrict__ b_lrf)
{
    __shared__ S1 s;
    const int n   = blockIdx.x;
    const int tid = threadIdx.x;

    // ---- Phase A ----
    if (tid < 36)                    s.ql[tid]      = q_lrf[n * 36 + tid];
    if (tid >= 64  && tid < 64+45)   s.kp[tid-64]   = kpt[tid - 64];
    if (tid >= 112 && tid < 115)     s.qp[tid-112]  = q_pts[n * 3 + (tid - 112)];
    if (tid >= 128 && tid < 160)     s.bl[tid-128]  = b_lrf[tid - 128];
    if (tid >= 160 && tid < 160+NNB) {
        int m   = tid - 160;
        int raw = nidx[n * NNB + m];
        bool ok = raw < SSUP;
        s.ic[m]   = ok ? raw : 0;
        s.mask[m] = ok ? 1.0f : 0.0f;
    }
    __syncthreads();

    // ---- Phase B: neighbor offsets ----
    if (tid < NNB) {
        int m = tid;
        int base = s.ic[m] * 3;
        s.nb[m][0] = s_pts[base + 0] - s.qp[0];
        s.nb[m][1] = s_pts[base + 1] - s.qp[1];
        s.nb[m][2] = s_pts[base + 2] - s.qp[2];
    }
    __syncthreads();

    // ---- Phase W: KP weights (tid<120) ----
    if (tid < 120) {
        int q = tid / 30, m = tid % 30;
        float a0 = 0.f, a1 = 0.f, a2 = 0.f;
        #pragma unroll
        for (int i = 0; i < 3; ++i) {
            float v = s.nb[m][i];
            a0 += v * s.ql[q*9 + i*3 + 0];
            a1 += v * s.ql[q*9 + i*3 + 1];
            a2 += v * s.ql[q*9 + i*3 + 2];
        }
        float msk = s.mask[m];
        #pragma unroll
        for (int k = 0; k < NKP; ++k) {
            float d0 = a0 - s.kp[k*3 + 0];
            float d1 = a1 - s.kp[k*3 + 1];
            float d2 = a2 - s.kp[k*3 + 2];
            float d  = sqrtf(d0*d0 + d1*d1 + d2*d2);
            s.w[q][m][k] = fmaxf(1.0f - d * EXT_INV, 0.0f) * msk;
        }
        s.w[q][m][15] = 0.0f;
    }

    // ---- Phase C: lrff[m][q][c] = sum_ki ql[q,ki]*T[ic[m]][ki][c] + b, masked ----
    if (tid < 240) {
        int m  = tid >> 3;          // 0..29
        int c4 = tid & 7;           // 0..7  -> channels c4*4..c4*4+3
        const float4* Tp = reinterpret_cast<const float4*>(g_T + (size_t)s.ic[m] * 288);
        float acc[4][4];
        #pragma unroll
        for (int q = 0; q < 4; ++q)
            #pragma unroll
            for (int j = 0; j < 4; ++j) acc[q][j] = 0.f;

        #pragma unroll
        for (int ki = 0; ki < 9; ++ki) {
            float4 t = __ldg(&Tp[ki * 8 + c4]);
            #pragma unroll
            for (int q = 0; q < 4; ++q) {
                float f = s.ql[q*9 + ki];
                acc[q][0] += f * t.x;
                acc[q][1] += f * t.y;
                acc[q][2] += f * t.z;
                acc[q][3] += f * t.w;
            }
        }
        float msk = s.mask[m];
        float4 b4 = *reinterpret_cast<const float4*>(&s.bl[c4 * 4]);
        #pragma unroll
        for (int q = 0; q < 4; ++q) {
            float4 v;
            v.x = (acc[q][0] + b4.x) * msk;
            v.y = (acc[q][1] + b4.y) * msk;
            v.z = (acc[q][2] + b4.z) * msk;
            v.w = (acc[q][3] + b4.w) * msk;
            *reinterpret_cast<float4*>(&s.lrff[m][q][c4 * 4]) = v;
        }
    }
    __syncthreads();

    // ---- Phase D: weighted[q][k][c] = sum_m w[q][k][m] * feat[q][m][c] ----
    {
        int q  = tid >> 6;
        int cg = (tid >> 2) & 15;
        int ks = tid & 3;
        float acc[4][4];
        #pragma unroll
        for (int i = 0; i < 4; ++i)
            #pragma unroll
            for (int j = 0; j < 4; ++j) acc[i][j] = 0.f;

        const float4* xp = reinterpret_cast<const float4*>(x);

        #pragma unroll 5
        for (int m = 0; m < NNB; ++m) {
            float4 f;
            if (cg < 8) {
                f = __ldg(&xp[(size_t)s.ic[m] * 32 + q * 8 + cg]);
                float msk = s.mask[m];
                f.x *= msk; f.y *= msk; f.z *= msk; f.w *= msk;
            } else {
                f = *reinterpret_cast<const float4*>(&s.lrff[m][q][(cg - 8) * 4]);
            }
            float4 wv = *reinterpret_cast<const float4*>(&s.w[q][m][ks * 4]);
            acc[0][0] += wv.x * f.x; acc[0][1] += wv.x * f.y; acc[0][2] += wv.x * f.z; acc[0][3] += wv.x * f.w;
            acc[1][0] += wv.y * f.x; acc[1][1] += wv.y * f.y; acc[1][2] += wv.y * f.z; acc[1][3] += wv.y * f.w;
            acc[2][0] += wv.z * f.x; acc[2][1] += wv.z * f.y; acc[2][2] += wv.z * f.z; acc[2][3] += wv.z * f.w;
            acc[3][0] += wv.w * f.x; acc[3][1] += wv.w * f.y; acc[3][2] += wv.w * f.z; acc[3][3] += wv.w * f.w;
        }

        // Store scratch pre-rounded to tf32 (stage2 skips cvt entirely).
        float4* outp = reinterpret_cast<float4*>(g_scratch + (size_t)n * KTOT);
        #pragma unroll
        for (int kk = 0; kk < 4; ++kk) {
            int k = ks * 4 + kk;
            if (k < NKP) {
                float4 v;
                v.x = __uint_as_float(f2tf32(acc[kk][0]));
                v.y = __uint_as_float(f2tf32(acc[kk][1]));
                v.z = __uint_as_float(f2tf32(acc[kk][2]));
                v.w = __uint_as_float(f2tf32(acc[kk][3]));
                outp[k * 64 + q * 16 + cg] = v;
            }
        }
    }
}

// ---------------------------------------------------------------------------
// Stage 2: tf32 mma.sync GEMM (inputs pre-rounded, no cvt in inner loop).
//   CTA 128x128x16, 8 warps (4m x 2n), warp tile 32x64, cp.async dbl-buffer.
// ---------------------------------------------------------------------------
#define S2_BM   128
#define S2_BN   128
#define S2_AST  20
#define S2_BST  132
#define S2_KIT  (KTOT / 16)   // 240

__global__ __launch_bounds__(256, 3)
void ekp_stage2_mma(const float* __restrict__ bias, float* __restrict__ out)
{
    __shared__ float As[2][S2_BM * S2_AST];
    __shared__ float Bs[2][16 * S2_BST];

    const int tid  = threadIdx.x;
    const int lane = tid & 31;
    const int wid  = tid >> 5;
    const int wm   = wid & 3;
    const int wn   = wid >> 2;
    const int gid  = lane >> 2;
    const int tig  = lane & 3;
    const int n0   = blockIdx.x * S2_BN;
    const int row0 = blockIdx.y * S2_BM;

    const uint32_t aSm = smem_u32(&As[0][0]);
    const uint32_t bSm = smem_u32(&Bs[0][0]);

    float acc[2][8][4];
    #pragma unroll
    for (int i = 0; i < 2; ++i)
        #pragma unroll
        for (int j = 0; j < 8; ++j)
            #pragma unroll
            for (int l = 0; l < 4; ++l) acc[i][j][l] = 0.f;

    int aR = tid >> 2, aC = tid & 3;
    int aRow0 = row0 + aR;           int aRow1 = row0 + aR + 64;
    if (aRow0 > NQPT - 1) aRow0 = NQPT - 1;
    if (aRow1 > NQPT - 1) aRow1 = NQPT - 1;
    const float* aG0 = g_scratch + (size_t)aRow0 * KTOT + aC * 4;
    const float* aG1 = g_scratch + (size_t)aRow1 * KTOT + aC * 4;
    uint32_t aS0 = aSm + (uint32_t)(aR * S2_AST + aC * 4) * 4;
    uint32_t aS1 = aSm + (uint32_t)((aR + 64) * S2_AST + aC * 4) * 4;
    int bR = tid >> 5, bC = tid & 31;
    const float* bG0 = g_Wc + (size_t)bR * COUTC + n0 + bC * 4;
    const float* bG1 = g_Wc + (size_t)(bR + 8) * COUTC + n0 + bC * 4;
    uint32_t bS0 = bSm + (uint32_t)(bR * S2_BST + bC * 4) * 4;
    uint32_t bS1 = bSm + (uint32_t)((bR + 8) * S2_BST + bC * 4) * 4;

    const uint32_t aBufStride = (uint32_t)(S2_BM * S2_AST) * 4;
    const uint32_t bBufStride = (uint32_t)(16 * S2_BST) * 4;

    auto load_tile = [&](int kt, int buf) {
        int k0 = kt * 16;
        cpa16(aS0 + buf * aBufStride, aG0 + k0);
        cpa16(aS1 + buf * aBufStride, aG1 + k0);
        cpa16(bS0 + buf * bBufStride, bG0 + (size_t)k0 * COUTC);
        cpa16(bS1 + buf * bBufStride, bG1 + (size_t)k0 * COUTC);
    };

    load_tile(0, 0);
    CP_COMMIT();

    for (int kt = 0; kt < S2_KIT; ++kt) {
        const int buf = kt & 1;
        if (kt + 1 < S2_KIT) {
            load_tile(kt + 1, buf ^ 1);
            CP_COMMIT();
            CP_WAIT1();
        } else {
            CP_WAIT0();
        }
        __syncthreads();

        const float* Ab = &As[buf][0];
        const float* Bb = &Bs[buf][0];
        #pragma unroll
        for (int ks = 0; ks < 16; ks += 8) {
            uint32_t a[2][4];
            #pragma unroll
            for (int mt = 0; mt < 2; ++mt) {
                int mbase = (wm * 32 + mt * 16 + gid) * S2_AST + ks + tig;
                a[mt][0] = __float_as_uint(Ab[mbase]);
                a[mt][1] = __float_as_uint(Ab[mbase + 8 * S2_AST]);
                a[mt][2] = __float_as_uint(Ab[mbase + 4]);
                a[mt][3] = __float_as_uint(Ab[mbase + 8 * S2_AST + 4]);
            }
            #pragma unroll
            for (int nt = 0; nt < 8; ++nt) {
                int nb = wn * 64 + nt * 8 + gid;
                uint32_t b[2];
                b[0] = __float_as_uint(Bb[(ks + tig) * S2_BST + nb]);
                b[1] = __float_as_uint(Bb[(ks + tig + 4) * S2_BST + nb]);
                mma16n8k8(acc[0][nt], a[0], b);
                mma16n8k8(acc[1][nt], a[1], b);
            }
        }
        __syncthreads();
    }

    // Epilogue: bias + LeakyReLU(0.1)
    #pragma unroll
    for (int mt = 0; mt < 2; ++mt) {
        int r0 = row0 + wm * 32 + mt * 16 + gid;
        #pragma unroll
        for (int nt = 0; nt < 8; ++nt) {
            int col = n0 + wn * 64 + nt * 8 + 2 * tig;
            float2 bb = *reinterpret_cast<const float2*>(&bias[col]);
            float v0 = acc[mt][nt][0] + bb.x;
            float v1 = acc[mt][nt][1] + bb.y;
            float v2 = acc[mt][nt][2] + bb.x;
            float v3 = acc[mt][nt][3] + bb.y;
            v0 = (v0 >= 0.f) ? v0 : 0.1f * v0;
            v1 = (v1 >= 0.f) ? v1 : 0.1f * v1;
            v2 = (v2 >= 0.f) ? v2 : 0.1f * v2;
            v3 = (v3 >= 0.f) ? v3 : 0.1f * v3;
            if (r0 < NQPT)
                *reinterpret_cast<float2*>(&out[(size_t)r0 * COUTC + col]) = make_float2(v0, v1);
            if (r0 + 8 < NQPT)
                *reinterpret_cast<float2*>(&out[(size_t)(r0 + 8) * COUTC + col]) = make_float2(v2, v3);
        }
    }
}

// ---------------------------------------------------------------------------
extern "C" void kernel_launch(void* const* d_in, const int* in_sizes, int n_in,
                              void* d_out, int out_size)
{
    const float* q_pts = (const float*)d_in[0];
    const float* s_pts = (const float*)d_in[1];
    const int*   nind  = (const int*)  d_in[2];
    const float* x     = (const float*)d_in[3];
    const float* q_lrf = (const float*)d_in[4];
    const float* s_lrf = (const float*)d_in[5];
    const float* kpt   = (const float*)d_in[6];
    const float* wts   = (const float*)d_in[7];
    const float* W_lrf = (const float*)d_in[8];
    const float* b_lrf = (const float*)d_in[9];
    const float* bias  = (const float*)d_in[10];
    float* out = (float*)d_out;

    conv_w<<<(KTOT * COUTC + 255) / 256, 256>>>(wts);
    build_T<<<(SSUP + 7) / 8, 256>>>(s_lrf, W_lrf);

    ekp_stage1<<<NQPT, 256>>>(q_pts, s_pts, nind, x, q_lrf, kpt, b_lrf);

    dim3 g2(COUTC / S2_BN, (NQPT + S2_BM - 1) / S2_BM);   // (2, 157)
    ekp_stage2_mma<<<g2, 256>>>(bias, out);
}

// round 5
// speedup vs baseline: 4.1765x; 1.1815x over previous
#include <cuda_runtime.h>
#include <math.h>
#include <stdint.h>

// Problem constants
#define NQPT   20000
#define SSUP   20000
#define NNB    30
#define NKP    15
#define EXT_INV 20.0f
#define KTOT   (NKP * 256)   // 3840
#define COUTC  256

__device__ float g_scratch[(size_t)NQPT * KTOT];   // tf32-rounded stage1 output
__device__ float g_T[(size_t)SSUP * 288];          // per-support LRF projection [spt][9][32]
__device__ float g_Wc[(size_t)KTOT * COUTC];       // tf32-rounded weights

// ---------------------------------------------------------------------------
// Helpers
// ---------------------------------------------------------------------------
static __device__ __forceinline__ uint32_t smem_u32(const void* p) {
    uint32_t a;
    asm("{ .reg .u64 t; cvta.to.shared.u64 t, %1; cvt.u32.u64 %0, t; }" : "=r"(a) : "l"(p));
    return a;
}
static __device__ __forceinline__ void cpa16(uint32_t s, const void* g) {
    asm volatile("cp.async.cg.shared.global [%0], [%1], 16;" :: "r"(s), "l"(g));
}
#define CP_COMMIT() asm volatile("cp.async.commit_group;" ::: "memory")
#define CP_WAIT1()  asm volatile("cp.async.wait_group 1;"  ::: "memory")
#define CP_WAIT0()  asm volatile("cp.async.wait_group 0;"  ::: "memory")

static __device__ __forceinline__ uint32_t f2tf32(float f) {
    uint32_t u;
    asm("cvt.rna.tf32.f32 %0, %1;" : "=r"(u) : "f"(f));
    return u;
}
static __device__ __forceinline__ void mma16n8k8(float* d, const uint32_t* a, const uint32_t* b) {
    asm volatile(
        "mma.sync.aligned.m16n8k8.row.col.f32.tf32.tf32.f32 "
        "{%0,%1,%2,%3}, {%4,%5,%6,%7}, {%8,%9}, {%0,%1,%2,%3};"
        : "+f"(d[0]), "+f"(d[1]), "+f"(d[2]), "+f"(d[3])
        : "r"(a[0]), "r"(a[1]), "r"(a[2]), "r"(a[3]), "r"(b[0]), "r"(b[1]));
}

// ---------------------------------------------------------------------------
// Prep A: T[spt][(k*3+i)][c] = sum_{s,j} s_lrf[spt][s*9+k*3+j] * W_lrf[(s*9+i*3+j)*32+c]
// ---------------------------------------------------------------------------
__global__ __launch_bounds__(256)
void build_T(const float* __restrict__ s_lrf, const float* __restrict__ W_lrf)
{
    __shared__ float Wsh[36 * 32];
    const int tid = threadIdx.x;
    for (int i = tid; i < 36 * 32; i += 256) Wsh[i] = W_lrf[i];
    __syncthreads();

    const int warp = tid >> 5, lane = tid & 31;
    const int spt = blockIdx.x * 8 + warp;
    if (spt >= SSUP) return;

    const float* sl = s_lrf + (size_t)spt * 36;
    float slr[36];
    #pragma unroll
    for (int i = 0; i < 36; ++i) slr[i] = __ldg(&sl[i]);

    float* Tout = g_T + (size_t)spt * 288;
    #pragma unroll
    for (int k = 0; k < 3; ++k) {
        #pragma unroll
        for (int i = 0; i < 3; ++i) {
            float acc = 0.f;
            #pragma unroll
            for (int s = 0; s < 4; ++s)
                #pragma unroll
                for (int j = 0; j < 3; ++j)
                    acc += slr[s*9 + k*3 + j] * Wsh[(s*9 + i*3 + j) * 32 + lane];
            Tout[(k*3 + i) * 32 + lane] = acc;
        }
    }
}

// Prep B: round weights to tf32 once
__global__ __launch_bounds__(256)
void conv_w(const float* __restrict__ W)
{
    size_t i = (size_t)blockIdx.x * 256 + threadIdx.x;
    if (i < (size_t)KTOT * COUTC)
        g_Wc[i] = __uint_as_float(f2tf32(W[i]));
}

// ---------------------------------------------------------------------------
// Stage 1: per-query block.
// ---------------------------------------------------------------------------
struct S1 {
    float w[4][NNB][16];
    float lrff[NNB][4][32];
    float ql[36];
    float kp[45];
    float qp[3];
    float bl[32];
    float nb[NNB][3];
    float mask[NNB];
    int   ic[NNB];
};

__global__ __launch_bounds__(256)
void ekp_stage1(const float* __restrict__ q_pts, const float* __restrict__ s_pts,
                const int*   __restrict__ nidx,  const float* __restrict__ x,
                const float* __restrict__ q_lrf, const float* __restrict__ kpt,
                const float* __restrict__ b_lrf)
{
    __shared__ S1 s;
    const int n   = blockIdx.x;
    const int tid = threadIdx.x;

    if (tid < 36)                    s.ql[tid]      = q_lrf[n * 36 + tid];
    if (tid >= 64  && tid < 64+45)   s.kp[tid-64]   = kpt[tid - 64];
    if (tid >= 112 && tid < 115)     s.qp[tid-112]  = q_pts[n * 3 + (tid - 112)];
    if (tid >= 128 && tid < 160)     s.bl[tid-128]  = b_lrf[tid - 128];
    if (tid >= 160 && tid < 160+NNB) {
        int m   = tid - 160;
        int raw = nidx[n * NNB + m];
        bool ok = raw < SSUP;
        s.ic[m]   = ok ? raw : 0;
        s.mask[m] = ok ? 1.0f : 0.0f;
    }
    __syncthreads();

    if (tid < NNB) {
        int m = tid;
        int base = s.ic[m] * 3;
        s.nb[m][0] = s_pts[base + 0] - s.qp[0];
        s.nb[m][1] = s_pts[base + 1] - s.qp[1];
        s.nb[m][2] = s_pts[base + 2] - s.qp[2];
    }
    __syncthreads();

    if (tid < 120) {
        int q = tid / 30, m = tid % 30;
        float a0 = 0.f, a1 = 0.f, a2 = 0.f;
        #pragma unroll
        for (int i = 0; i < 3; ++i) {
            float v = s.nb[m][i];
            a0 += v * s.ql[q*9 + i*3 + 0];
            a1 += v * s.ql[q*9 + i*3 + 1];
            a2 += v * s.ql[q*9 + i*3 + 2];
        }
        float msk = s.mask[m];
        #pragma unroll
        for (int k = 0; k < NKP; ++k) {
            float d0 = a0 - s.kp[k*3 + 0];
            float d1 = a1 - s.kp[k*3 + 1];
            float d2 = a2 - s.kp[k*3 + 2];
            float d  = sqrtf(d0*d0 + d1*d1 + d2*d2);
            s.w[q][m][k] = fmaxf(1.0f - d * EXT_INV, 0.0f) * msk;
        }
        s.w[q][m][15] = 0.0f;
    }

    if (tid < 240) {
        int m  = tid >> 3;
        int c4 = tid & 7;
        const float4* Tp = reinterpret_cast<const float4*>(g_T + (size_t)s.ic[m] * 288);
        float acc[4][4];
        #pragma unroll
        for (int q = 0; q < 4; ++q)
            #pragma unroll
            for (int j = 0; j < 4; ++j) acc[q][j] = 0.f;

        #pragma unroll
        for (int ki = 0; ki < 9; ++ki) {
            float4 t = __ldg(&Tp[ki * 8 + c4]);
            #pragma unroll
            for (int q = 0; q < 4; ++q) {
                float f = s.ql[q*9 + ki];
                acc[q][0] += f * t.x;
                acc[q][1] += f * t.y;
                acc[q][2] += f * t.z;
                acc[q][3] += f * t.w;
            }
        }
        float msk = s.mask[m];
        float4 b4 = *reinterpret_cast<const float4*>(&s.bl[c4 * 4]);
        #pragma unroll
        for (int q = 0; q < 4; ++q) {
            float4 v;
            v.x = (acc[q][0] + b4.x) * msk;
            v.y = (acc[q][1] + b4.y) * msk;
            v.z = (acc[q][2] + b4.z) * msk;
            v.w = (acc[q][3] + b4.w) * msk;
            *reinterpret_cast<float4*>(&s.lrff[m][q][c4 * 4]) = v;
        }
    }
    __syncthreads();

    {
        int q  = tid >> 6;
        int cg = (tid >> 2) & 15;
        int ks = tid & 3;
        float acc[4][4];
        #pragma unroll
        for (int i = 0; i < 4; ++i)
            #pragma unroll
            for (int j = 0; j < 4; ++j) acc[i][j] = 0.f;

        const float4* xp = reinterpret_cast<const float4*>(x);

        #pragma unroll 5
        for (int m = 0; m < NNB; ++m) {
            float4 f;
            if (cg < 8) {
                f = __ldg(&xp[(size_t)s.ic[m] * 32 + q * 8 + cg]);
                float msk = s.mask[m];
                f.x *= msk; f.y *= msk; f.z *= msk; f.w *= msk;
            } else {
                f = *reinterpret_cast<const float4*>(&s.lrff[m][q][(cg - 8) * 4]);
            }
            float4 wv = *reinterpret_cast<const float4*>(&s.w[q][m][ks * 4]);
            acc[0][0] += wv.x * f.x; acc[0][1] += wv.x * f.y; acc[0][2] += wv.x * f.z; acc[0][3] += wv.x * f.w;
            acc[1][0] += wv.y * f.x; acc[1][1] += wv.y * f.y; acc[1][2] += wv.y * f.z; acc[1][3] += wv.y * f.w;
            acc[2][0] += wv.z * f.x; acc[2][1] += wv.z * f.y; acc[2][2] += wv.z * f.z; acc[2][3] += wv.z * f.w;
            acc[3][0] += wv.w * f.x; acc[3][1] += wv.w * f.y; acc[3][2] += wv.w * f.z; acc[3][3] += wv.w * f.w;
        }

        float4* outp = reinterpret_cast<float4*>(g_scratch + (size_t)n * KTOT);
        #pragma unroll
        for (int kk = 0; kk < 4; ++kk) {
            int k = ks * 4 + kk;
            if (k < NKP) {
                float4 v;
                v.x = __uint_as_float(f2tf32(acc[kk][0]));
                v.y = __uint_as_float(f2tf32(acc[kk][1]));
                v.z = __uint_as_float(f2tf32(acc[kk][2]));
                v.w = __uint_as_float(f2tf32(acc[kk][3]));
                outp[k * 64 + q * 16 + cg] = v;
            }
        }
    }
}

// ---------------------------------------------------------------------------
// Stage 2: tf32 mma.sync GEMM, 2x2 warp grid, 64x64 warp tile, BK=32, 3-stage.
//   CTA 128x128, 128 threads. Dynamic smem.
// ---------------------------------------------------------------------------
#define S2_BM   128
#define S2_BN   128
#define S2_BK   32
#define S2_AST  36     // A smem row stride (floats)
#define S2_BST  132    // B smem row stride (floats)
#define S2_KIT  (KTOT / S2_BK)   // 120
#define S2_AELT (S2_BM * S2_AST)             // 4608 floats / stage
#define S2_BELT (S2_BK * S2_BST)             // 4224 floats / stage
#define S2_SMEM ((3 * (S2_AELT + S2_BELT)) * 4)   // 105984 B

__global__ __launch_bounds__(128, 2)
void ekp_stage2_mma(const float* __restrict__ bias, float* __restrict__ out)
{
    extern __shared__ float sm[];
    float* Asm = sm;                      // 3 stages of A
    float* Bsm = sm + 3 * S2_AELT;        // 3 stages of B

    const int tid  = threadIdx.x;
    const int lane = tid & 31;
    const int wid  = tid >> 5;
    const int wm   = wid & 1;        // warp m index (0..1)
    const int wn   = wid >> 1;       // warp n index (0..1)
    const int gid  = lane >> 2;      // 0..7
    const int tig  = lane & 3;       // 0..3
    const int n0   = blockIdx.x * S2_BN;
    const int row0 = blockIdx.y * S2_BM;

    const uint32_t aSm = smem_u32(Asm);
    const uint32_t bSm = smem_u32(Bsm);

    float acc[4][8][4];
    #pragma unroll
    for (int i = 0; i < 4; ++i)
        #pragma unroll
        for (int j = 0; j < 8; ++j)
            #pragma unroll
            for (int l = 0; l < 4; ++l) acc[i][j][l] = 0.f;

    // A tile 128x32: 1024 f4 chunks; 8 per thread. chunk -> (r=idx>>3, c4=idx&7)
    // B tile 32x128: 1024 f4 chunks; 8 per thread. chunk -> (r=idx>>5, c4=idx&31)
    const int aR = tid >> 3, aC = tid & 7;   // base chunk (stride 128 chunks => +16 rows)
    const int bR = tid >> 5, bC = tid & 31;

    auto load_tile = [&](int kt, int st) {
        const int k0 = kt * S2_BK;
        const uint32_t aBase = aSm + (uint32_t)(st * S2_AELT) * 4;
        const uint32_t bBase = bSm + (uint32_t)(st * S2_BELT) * 4;
        #pragma unroll
        for (int i = 0; i < 8; ++i) {
            int r = aR + i * 16;
            int grow = row0 + r;
            if (grow > NQPT - 1) grow = NQPT - 1;
            cpa16(aBase + (uint32_t)(r * S2_AST + aC * 4) * 4,
                  g_scratch + (size_t)grow * KTOT + k0 + aC * 4);
        }
        #pragma unroll
        for (int i = 0; i < 8; ++i) {
            int r = bR + i * 4;
            cpa16(bBase + (uint32_t)(r * S2_BST + bC * 4) * 4,
                  g_Wc + (size_t)(k0 + r) * COUTC + n0 + bC * 4);
        }
    };

    load_tile(0, 0); CP_COMMIT();
    load_tile(1, 1); CP_COMMIT();

    for (int kt = 0; kt < S2_KIT; ++kt) {
        if (kt + 1 < S2_KIT) { CP_WAIT1(); } else { CP_WAIT0(); }
        __syncthreads();

        const int buf = kt % 3;
        if (kt + 2 < S2_KIT) {
            load_tile(kt + 2, (kt + 2) % 3);
            CP_COMMIT();
        }

        const float* Ab = Asm + buf * S2_AELT;
        const float* Bb = Bsm + buf * S2_BELT;

        #pragma unroll
        for (int ks = 0; ks < S2_BK; ks += 8) {
            uint32_t a[4][4];
            #pragma unroll
            for (int mt = 0; mt < 4; ++mt) {
                int mbase = (wm * 64 + mt * 16 + gid) * S2_AST + ks + tig;
                a[mt][0] = __float_as_uint(Ab[mbase]);
                a[mt][1] = __float_as_uint(Ab[mbase + 8 * S2_AST]);
                a[mt][2] = __float_as_uint(Ab[mbase + 4]);
                a[mt][3] = __float_as_uint(Ab[mbase + 8 * S2_AST + 4]);
            }
            uint32_t b[8][2];
            #pragma unroll
            for (int nt = 0; nt < 8; ++nt) {
                int nb = wn * 64 + nt * 8 + gid;
                b[nt][0] = __float_as_uint(Bb[(ks + tig) * S2_BST + nb]);
                b[nt][1] = __float_as_uint(Bb[(ks + tig + 4) * S2_BST + nb]);
            }
            #pragma unroll
            for (int mt = 0; mt < 4; ++mt)
                #pragma unroll
                for (int nt = 0; nt < 8; ++nt)
                    mma16n8k8(acc[mt][nt], a[mt], b[nt]);
        }
        __syncthreads();
    }

    // Epilogue: bias + LeakyReLU(0.1)
    #pragma unroll
    for (int mt = 0; mt < 4; ++mt) {
        int r0 = row0 + wm * 64 + mt * 16 + gid;
        #pragma unroll
        for (int nt = 0; nt < 8; ++nt) {
            int col = n0 + wn * 64 + nt * 8 + 2 * tig;
            float2 bb = *reinterpret_cast<const float2*>(&bias[col]);
            float v0 = acc[mt][nt][0] + bb.x;
            float v1 = acc[mt][nt][1] + bb.y;
            float v2 = acc[mt][nt][2] + bb.x;
            float v3 = acc[mt][nt][3] + bb.y;
            v0 = (v0 >= 0.f) ? v0 : 0.1f * v0;
            v1 = (v1 >= 0.f) ? v1 : 0.1f * v1;
            v2 = (v2 >= 0.f) ? v2 : 0.1f * v2;
            v3 = (v3 >= 0.f) ? v3 : 0.1f * v3;
            if (r0 < NQPT)
                *reinterpret_cast<float2*>(&out[(size_t)r0 * COUTC + col]) = make_float2(v0, v1);
            if (r0 + 8 < NQPT)
                *reinterpret_cast<float2*>(&out[(size_t)(r0 + 8) * COUTC + col]) = make_float2(v2, v3);
        }
    }
}

// ---------------------------------------------------------------------------
extern "C" void kernel_launch(void* const* d_in, const int* in_sizes, int n_in,
                              void* d_out, int out_size)
{
    const float* q_pts = (const float*)d_in[0];
    const float* s_pts = (const float*)d_in[1];
    const int*   nind  = (const int*)  d_in[2];
    const float* x     = (const float*)d_in[3];
    const float* q_lrf = (const float*)d_in[4];
    const float* s_lrf = (const float*)d_in[5];
    const float* kpt   = (const float*)d_in[6];
    const float* wts   = (const float*)d_in[7];
    const float* W_lrf = (const float*)d_in[8];
    const float* b_lrf = (const float*)d_in[9];
    const float* bias  = (const float*)d_in[10];
    float* out = (float*)d_out;

    cudaFuncSetAttribute(ekp_stage2_mma, cudaFuncAttributeMaxDynamicSharedMemorySize, S2_SMEM);

    conv_w<<<(KTOT * COUTC + 255) / 256, 256>>>(wts);
    build_T<<<(SSUP + 7) / 8, 256>>>(s_lrf, W_lrf);

    ekp_stage1<<<NQPT, 256>>>(q_pts, s_pts, nind, x, q_lrf, kpt, b_lrf);

    dim3 g2(COUTC / S2_BN, (NQPT + S2_BM - 1) / S2_BM);   // (2, 157)
    ekp_stage2_mma<<<g2, 256 / 2, S2_SMEM>>>(bias, out);
}